// round 15
// baseline (speedup 1.0000x reference)
#include <cuda_runtime.h>
#include <cuda_bf16.h>
#include <cuda_fp16.h>
#include <cstddef>
#include <cstdint>

// ---------------------------------------------------------------------------
// TransNet, mma.sync fp16 GEMM, persistent-tile grid (no wave quantization).
//   Layer solve:  v·(cI + dt^2 W^T W) = rhs_v + dt·rhs_u@W
//   u_out = -u = dt·v@W^T - rhs_u,  v_out = -v
//   (cI + dt^2 K)^{-1} ≈ (1/c)(I - aK)   [first-order Neumann]
// All-fp16 dataflow (fp32 only for K and logits). Minv stored as 1024*Minv.
// Block 128x64, BK=64 (128B rows, SW128), 8 warps 32x32, 3-stage, 3 CTA/SM.
// ---------------------------------------------------------------------------

#define BATCH   8192
#define UNITS   1024
#define INDIM   2048
#define OUTDIM  1000
#define U2      (UNITS * UNITS)
#define PERSIST (148 * 3)

static const float DT     = 0.1f;
static const float CCONST = 11.0f;           // 1 + dt/eps
static const float ACONST = 0.01f / 11.0f;   // dt^2 / c

// ------------------------------- scratch (16B+ aligned) --------------------
__device__ __align__(256) float g_s1[3 * U2];                    // K fp32 x3

__device__ __align__(256) unsigned short g_x16[BATCH * INDIM];   // fp16 x
__device__ __align__(256) unsigned short g_win16[UNITS * INDIM]; // fp16 W_in
__device__ __align__(256) unsigned short g_wo16[OUTDIM * UNITS]; // fp16 W_out
__device__ __align__(256) unsigned short g_P0[BATCH * UNITS];    // fp16 act
__device__ __align__(256) unsigned short g_P1[BATCH * UNITS];    // fp16 act
__device__ __align__(256) unsigned short g_P2[BATCH * UNITS];    // fp16 V
__device__ __align__(256) unsigned short g_rv16[BATCH * UNITS];  // fp16 Rv
__device__ __align__(256) unsigned short g_w16[3 * U2];          // fp16 W x3
__device__ __align__(256) unsigned short g_t16[3 * U2];          // fp16 W^T x3
__device__ __align__(256) unsigned short g_mi16[3 * U2];         // fp16 1024*Minv x3

// ------------------------------ helpers ------------------------------------
__device__ __forceinline__ uint32_t smem_u32(const void* p) {
    uint32_t a;
    asm("{ .reg .u64 t; cvta.to.shared.u64 t, %1; cvt.u32.u64 %0, t; }"
        : "=r"(a) : "l"(p));
    return a;
}

__device__ __forceinline__ void cp16(uint32_t dst, const void* src, bool inb) {
    int sz = inb ? 16 : 0;
    asm volatile(
        "{\n\t.reg .u64 g;\n\tcvta.to.global.u64 g, %1;\n\t"
        "cp.async.cg.shared.global [%0], [g], 16, %2;\n\t}"
        :: "r"(dst), "l"(src), "r"(sz) : "memory");
}
__device__ __forceinline__ void cp_commit() {
    asm volatile("cp.async.commit_group;" ::: "memory");
}
__device__ __forceinline__ void cp_wait1() {
    asm volatile("cp.async.wait_group 1;" ::: "memory");
}

__device__ __forceinline__ void mma_h(float* d, const uint32_t* a, const uint32_t* b) {
    asm volatile(
        "mma.sync.aligned.m16n8k16.row.col.f32.f16.f16.f32 "
        "{%0,%1,%2,%3}, {%4,%5,%6,%7}, {%8,%9}, {%0,%1,%2,%3};"
        : "+f"(d[0]), "+f"(d[1]), "+f"(d[2]), "+f"(d[3])
        : "r"(a[0]), "r"(a[1]), "r"(a[2]), "r"(a[3]), "r"(b[0]), "r"(b[1]));
}

__device__ __forceinline__ void ldsm4(uint32_t* r, uint32_t addr) {
    asm volatile("ldmatrix.sync.aligned.m8n8.x4.shared.b16 {%0,%1,%2,%3}, [%4];"
        : "=r"(r[0]), "=r"(r[1]), "=r"(r[2]), "=r"(r[3]) : "r"(addr));
}

__device__ __forceinline__ unsigned short f2h(float x) {
    return __half_as_ushort(__float2half_rn(x));
}
__device__ __forceinline__ float h2f(unsigned short x) {
    return __half2float(__ushort_as_half(x));
}

// --------------------------- GEMM kernel -------------------------------------
// Persistent tiles: t = blockIdx.x .. ntiles step gridDim.x; t -> (z, by, bx).
// d[m,n] = alpha*sum_k A[m,k]B[n,k] (+bias[n]) (+add_scale*fp16 addp16[m,n])
// Plain mode (bias2==null): C=d fp32 (opt), Ch=fp16(d) (opt).
// rhs mode (bias2!=null):   Ru = d + 0.1*bias2[n]; Ch=fp16(Ru);
//                           Rv = 10*relu(d) + (vprev16? svv*vprev16 : relu(d));
//                           Crelu16=fp16(Rv).
// Block 128x64, BK=64 (128B rows, SW128); 8 warps, warp tile 32x32.
#define BM 128
#define BN 64
#define BK 64
#define A_T 16384u
#define STAGE 24576u
#define NSTAGE 3
#define SM_H (1024 + NSTAGE * STAGE)    // 74752

__global__ __launch_bounds__(256, 3) void gemm_h16(
    const unsigned short* __restrict__ A, const unsigned short* __restrict__ B,
    float* __restrict__ C, unsigned short* __restrict__ Ch,
    unsigned short* __restrict__ Crelu16,
    int M, int N, int K, float alpha,
    const float* __restrict__ bias,
    const unsigned short* __restrict__ addp16, float add_scale,
    const float* __restrict__ bias2,
    const unsigned short* __restrict__ vprev16, float svv,
    long zsA, long zsB, long zsC,
    int ntx, int nty, int ntiles)
{
    extern __shared__ char smem[];
    const uint32_t sbase = smem_u32(smem) + 1024;
    const int tid  = threadIdx.x;
    const int wid  = tid >> 5;
    const int lane = tid & 31;

    // tile-invariant per-thread constants
    const int arow = tid >> 3;          // 0..31
    const int ach  = tid & 7;           // 16B chunk in 128B row
    const uint32_t of0 = (uint32_t)arow * 128u
                       + (uint32_t)((ach ^ (arow & 7)) << 4);
    const int wm = wid & 3;
    const int wn = wid >> 2;
    const int r  = lane >> 2;
    const int c2 = (lane & 3) * 2;
    const int q    = lane >> 3;
    const int rin  = lane & 7;
    const uint32_t a_row = (uint32_t)(wm * 32 + (q & 1) * 8 + rin) * 128u;
    const int a_sel = q >> 1;
    const uint32_t b_row = (uint32_t)(wn * 32 + (q >> 1) * 8 + rin) * 128u + A_T;
    const int b_sel = q & 1;
    const int nc = K / BK;
    const int ntxy = ntx * nty;

    for (int t = blockIdx.x; t < ntiles; t += gridDim.x) {
        const int z   = t / ntxy;
        const int rem = t - z * ntxy;
        const int bm  = (rem / ntx) * BM;
        const int bn  = (rem % ntx) * BN;

        const unsigned short* pA = A + (long)z * zsA;
        const unsigned short* pB = B + (long)z * zsB;
        const unsigned short* gA = pA + (size_t)(bm + arow) * K + ach * 8;
        const unsigned short* gB = pB + (size_t)(bn + arow) * K + ach * 8;
        const size_t rstep = (size_t)32 * K;
        bool inA[4], inB[2];
#pragma unroll
        for (int i = 0; i < 4; ++i) inA[i] = (bm + arow + 32 * i) < M;
#pragma unroll
        for (int i = 0; i < 2; ++i) inB[i] = (bn + arow + 32 * i) < N;

        auto issue_stage = [&](int c) {
            const int k0 = c * BK;
            const uint32_t sd = sbase + (uint32_t)(c % NSTAGE) * STAGE;
#pragma unroll
            for (int i = 0; i < 4; ++i)
                cp16(sd + of0 + (uint32_t)i * 4096u, gA + (size_t)i * rstep + k0, inA[i]);
#pragma unroll
            for (int i = 0; i < 2; ++i)
                cp16(sd + A_T + of0 + (uint32_t)i * 4096u, gB + (size_t)i * rstep + k0, inB[i]);
            cp_commit();
        };

        float acc[2][4][4];
#pragma unroll
        for (int a = 0; a < 2; ++a)
#pragma unroll
            for (int b = 0; b < 4; ++b)
#pragma unroll
                for (int k = 0; k < 4; ++k) acc[a][b][k] = 0.0f;

        issue_stage(0);
        if (nc > 1) issue_stage(1);

        for (int c = 0; c < nc; ++c) {
            cp_wait1();
            __syncthreads();
            if (c + 2 < nc) issue_stage(c + 2);

            const uint32_t st = sbase + (uint32_t)(c % NSTAGE) * STAGE;

#pragma unroll
            for (int ks = 0; ks < 4; ++ks) {
                const uint32_t aoff = (uint32_t)(((ks * 2 + a_sel) ^ rin)) << 4;
                const uint32_t boff = (uint32_t)(((ks * 2 + b_sel) ^ rin)) << 4;

                uint32_t a[2][4];
                ldsm4(a[0], st + a_row + aoff);
                ldsm4(a[1], st + a_row + 2048u + aoff);

                uint32_t b[4][2];
#pragma unroll
                for (int p = 0; p < 2; ++p) {
                    uint32_t r4[4];
                    ldsm4(r4, st + b_row + (uint32_t)p * 2048u + boff);
                    b[2 * p][0] = r4[0]; b[2 * p][1] = r4[1];
                    b[2 * p + 1][0] = r4[2]; b[2 * p + 1][1] = r4[3];
                }

#pragma unroll
                for (int nt = 0; nt < 4; ++nt) {
                    mma_h(acc[0][nt], a[0], b[nt]);
                    mma_h(acc[1][nt], a[1], b[nt]);
                }
            }
        }
        __syncthreads();   // all MMAs done; smem stages reusable next tile

        // ---- epilogue -------------------------------------------------------
        float* pC = C ? C + (long)z * zsC : nullptr;
        unsigned short* pCh = Ch ? Ch + (long)z * zsC : nullptr;
        unsigned short* pCr = Crelu16 ? Crelu16 + (long)z * zsC : nullptr;
#pragma unroll
        for (int mt = 0; mt < 2; ++mt) {
#pragma unroll
            for (int nt = 0; nt < 4; ++nt) {
                const int col = bn + wn * 32 + nt * 8 + c2;
                if (col >= N) continue;
                float bx0 = 0.f, by0 = 0.f;
                if (bias) { bx0 = bias[col]; by0 = bias[col + 1]; }
#pragma unroll
                for (int h = 0; h < 2; ++h) {
                    const int m = bm + wm * 32 + mt * 16 + r + h * 8;
                    float d0 = alpha * acc[mt][nt][2 * h + 0] + bx0;
                    float d1 = alpha * acc[mt][nt][2 * h + 1] + by0;
                    size_t idx = (size_t)m * N + col;
                    if (addp16) {
                        ushort2 ap = *(const ushort2*)(addp16 + idx);
                        d0 += add_scale * h2f(ap.x);
                        d1 += add_scale * h2f(ap.y);
                    }
                    if (bias2) {
                        float r0 = fmaxf(d0, 0.f), r1 = fmaxf(d1, 0.f);
                        float rv0 = 10.f * r0, rv1 = 10.f * r1;
                        if (vprev16) {
                            ushort2 vp = *(const ushort2*)(vprev16 + idx);
                            rv0 += svv * h2f(vp.x); rv1 += svv * h2f(vp.y);
                        } else {
                            rv0 += r0; rv1 += r1;
                        }
                        *(ushort2*)(pCr + idx) = make_ushort2(f2h(rv0), f2h(rv1));
                        d0 += 0.1f * bias2[col];
                        d1 += 0.1f * bias2[col + 1];
                    }
                    if (pC)  *(float2*)(pC + idx) = make_float2(d0, d1);
                    if (pCh) *(ushort2*)(pCh + idx) = make_ushort2(f2h(d0), f2h(d1));
                }
            }
        }
    }
}

// ----------------------------- elementwise ---------------------------------
__global__ void tofp16(const float* __restrict__ src,
                       unsigned short* __restrict__ dst, int n)
{
    int i = blockIdx.x * blockDim.x + threadIdx.x;
    if (i * 4 < n) {
        float4 v = *(const float4*)(src + i * 4);
        *(ushort4*)(dst + i * 4) =
            make_ushort4(f2h(v.x), f2h(v.y), f2h(v.z), f2h(v.w));
    }
}

__global__ void weight_prep3(unsigned short* __restrict__ w16,
                             unsigned short* __restrict__ t16,
                             const float* __restrict__ W0,
                             const float* __restrict__ W1,
                             const float* __restrict__ W2, int n)
{
    __shared__ float t[32][33];
    const int z = blockIdx.z;
    const float* W = (z == 0) ? W0 : (z == 1) ? W1 : W2;
    unsigned short* w = w16 + (size_t)z * U2;
    unsigned short* tt = t16 + (size_t)z * U2;
    int x = blockIdx.x * 32 + threadIdx.x;
    int y = blockIdx.y * 32 + threadIdx.y;
    float v = W[(size_t)y * n + x];
    t[threadIdx.y][threadIdx.x] = v;
    w[(size_t)y * n + x] = f2h(v);
    __syncthreads();
    int ox = blockIdx.y * 32 + threadIdx.x;
    int oy = blockIdx.x * 32 + threadIdx.y;
    tt[(size_t)oy * n + ox] = f2h(t[threadIdx.x][threadIdx.y]);
}

__global__ void scale_diag16(unsigned short* __restrict__ d16,
                             const float* __restrict__ src,
                             float scale, float diag, int dim, int total)
{
    int i = blockIdx.x * blockDim.x + threadIdx.x;
    if (i < total) {
        float v = scale * src[i];
        int row = (i / dim) % dim;
        if (row == (i % dim)) v += diag;
        d16[i] = f2h(v);
    }
}

__global__ void softmax_rows(float* __restrict__ data, int cols)
{
    int row = blockIdx.x;
    float* d = data + (size_t)row * cols;
    __shared__ float sm[32];
    int tid = threadIdx.x, lane = tid & 31, warp = tid >> 5;
    int nwarp = blockDim.x >> 5;

    float m = -3.4e38f;
    for (int i = tid; i < cols; i += blockDim.x) m = fmaxf(m, d[i]);
#pragma unroll
    for (int o = 16; o; o >>= 1) m = fmaxf(m, __shfl_xor_sync(0xffffffffu, m, o));
    if (lane == 0) sm[warp] = m;
    __syncthreads();
    if (warp == 0) {
        float t = (lane < nwarp) ? sm[lane] : -3.4e38f;
#pragma unroll
        for (int o = 16; o; o >>= 1) t = fmaxf(t, __shfl_xor_sync(0xffffffffu, t, o));
        if (lane == 0) sm[0] = t;
    }
    __syncthreads();
    float mx = sm[0];
    __syncthreads();

    float s = 0.0f;
    for (int i = tid; i < cols; i += blockDim.x) {
        float e = expf(d[i] - mx);
        d[i] = e;
        s += e;
    }
#pragma unroll
    for (int o = 16; o; o >>= 1) s += __shfl_xor_sync(0xffffffffu, s, o);
    if (lane == 0) sm[warp] = s;
    __syncthreads();
    if (warp == 0) {
        float t = (lane < nwarp) ? sm[lane] : 0.0f;
#pragma unroll
        for (int o = 16; o; o >>= 1) t += __shfl_xor_sync(0xffffffffu, t, o);
        if (lane == 0) sm[0] = t;
    }
    __syncthreads();
    float inv = 1.0f / sm[0];
    for (int i = tid; i < cols; i += blockDim.x) d[i] *= inv;
}

// ---------------------------------------------------------------------------
static inline int grid_for(int ntiles) {
    return ntiles < PERSIST ? ntiles : PERSIST;
}

extern "C" void kernel_launch(void* const* d_in, const int* in_sizes, int n_in,
                              void* d_out, int out_size)
{
    const float* x     = (const float*)d_in[0];
    const float* W_in  = (const float*)d_in[1];
    const float* b_in  = (const float*)d_in[2];
    const float* Ws[3] = {(const float*)d_in[3], (const float*)d_in[5], (const float*)d_in[7]};
    const float* bs[3] = {(const float*)d_in[4], (const float*)d_in[6], (const float*)d_in[8]};
    const float* W_out = (const float*)d_in[9];
    const float* b_out = (const float*)d_in[10];
    float* out = (float*)d_out;

    cudaFuncSetAttribute(gemm_h16, cudaFuncAttributeMaxDynamicSharedMemorySize, SM_H);

    float* s1;
    cudaGetSymbolAddress((void**)&s1, g_s1);
    unsigned short *x16, *win16, *wo16, *P0, *P1, *P2, *rv16, *w16, *t16, *mi16;
    cudaGetSymbolAddress((void**)&x16, g_x16);
    cudaGetSymbolAddress((void**)&win16, g_win16);
    cudaGetSymbolAddress((void**)&wo16, g_wo16);
    cudaGetSymbolAddress((void**)&P0, g_P0);
    cudaGetSymbolAddress((void**)&P1, g_P1);
    cudaGetSymbolAddress((void**)&P2, g_P2);
    cudaGetSymbolAddress((void**)&rv16, g_rv16);
    cudaGetSymbolAddress((void**)&w16, g_w16);
    cudaGetSymbolAddress((void**)&t16, g_t16);
    cudaGetSymbolAddress((void**)&mi16, g_mi16);

    // tile counts
    const int ntxU = UNITS / BN;                       // 16
    const int ntyB = BATCH / BM;                       // 64
    const int ntyU = UNITS / BM;                       // 8
    const int ntxO = (OUTDIM + BN - 1) / BN;           // 16
    const int ntBig = ntxU * ntyB;                     // 1024
    const int ntK   = ntxU * ntyU * 3;                 // 384
    const int ntOut = ntxO * ntyB;                     // 1024

    dim3 tblk(32, 32), tgrid3(UNITS / 32, UNITS / 32, 3);

    // one-time fp16 conversions + batched weight pipeline
    tofp16<<<(BATCH * INDIM / 4 + 255) / 256, 256>>>(x, x16, BATCH * INDIM);
    tofp16<<<(UNITS * INDIM / 4 + 255) / 256, 256>>>(W_in, win16, UNITS * INDIM);
    tofp16<<<(OUTDIM * UNITS / 4 + 255) / 256, 256>>>(W_out, wo16, OUTDIM * UNITS);
    weight_prep3<<<tgrid3, tblk>>>(w16, t16, Ws[0], Ws[1], Ws[2], UNITS);
    // K_z = W_z^T W_z  (batched, fp32 out)
    gemm_h16<<<grid_for(ntK), 256, SM_H>>>(t16, t16, s1, nullptr, nullptr,
                                           UNITS, UNITS, UNITS, 1.0f, nullptr,
                                           nullptr, 0.0f, nullptr, nullptr, 0.0f,
                                           (long)U2, (long)U2, (long)U2,
                                           ntxU, ntyU, ntK);
    // mi16_z = fp16(1024 * Minv_z)
    scale_diag16<<<(3 * U2 + 255) / 256, 256>>>(mi16, s1,
                                                -1024.0f * ACONST / CCONST,
                                                1024.0f / CCONST, UNITS, 3 * U2);

    // Input GEMM, rhs mode: d = x@W_in^T + b_in
    //   Ru0 fp16 -> P0, Rv0 = 11*relu(d) fp16 -> rv16
    gemm_h16<<<grid_for(ntBig), 256, SM_H>>>(x16, win16, nullptr, P0, rv16,
                                             BATCH, UNITS, INDIM, 1.0f, b_in,
                                             nullptr, 0.0f, bs[0], nullptr, 0.0f,
                                             0, 0, 0, ntxU, ntyB, ntBig);

    unsigned short* ru = P0;      // fp16 Ru_l
    unsigned short* sc = P1;      // fp16 scratch (r, then next Ru)

    for (int l = 0; l < 3; ++l) {
        unsigned short* wl  = w16  + (size_t)l * U2;
        unsigned short* tl  = t16  + (size_t)l * U2;
        unsigned short* mil = mi16 + (size_t)l * U2;

        // r = dt*Ru@W + Rv  (B = W^T) -> fp16 sc
        gemm_h16<<<grid_for(ntBig), 256, SM_H>>>(ru, tl, nullptr, sc, nullptr,
                                                 BATCH, UNITS, UNITS, DT, nullptr,
                                                 rv16, 1.0f, nullptr, nullptr, 0.0f,
                                                 0, 0, 0, ntxU, ntyB, ntBig);
        // V = r @ (1024*Minv) / 1024 -> fp16 P2
        gemm_h16<<<grid_for(ntBig), 256, SM_H>>>(sc, mil, nullptr, P2, nullptr,
                                                 BATCH, UNITS, UNITS, 1.0f / 1024.0f,
                                                 nullptr, nullptr, 0.0f,
                                                 nullptr, nullptr, 0.0f,
                                                 0, 0, 0, ntxU, ntyB, ntBig);
        // u_out = dt*V@W^T - Ru ; rhs mode emits Ru_{l+1} fp16 -> sc, Rv -> rv16
        if (l < 2) {
            gemm_h16<<<grid_for(ntBig), 256, SM_H>>>(P2, wl, nullptr, sc, rv16,
                                                     BATCH, UNITS, UNITS, DT, nullptr,
                                                     ru, -1.0f, bs[l + 1], P2, -1.0f,
                                                     0, 0, 0, ntxU, ntyB, ntBig);
        } else {
            gemm_h16<<<grid_for(ntBig), 256, SM_H>>>(P2, wl, nullptr, sc, nullptr,
                                                     BATCH, UNITS, UNITS, DT, nullptr,
                                                     ru, -1.0f, nullptr, nullptr, 0.0f,
                                                     0, 0, 0, ntxU, ntyB, ntBig);
        }
        unsigned short* t = ru; ru = sc; sc = t;
    }

    // logits = u @ W_out^T + b_out -> out ; softmax
    gemm_h16<<<grid_for(ntOut), 256, SM_H>>>(ru, wo16, out, nullptr, nullptr,
                                             BATCH, OUTDIM, UNITS, 1.0f, b_out,
                                             nullptr, 0.0f, nullptr, nullptr, 0.0f,
                                             0, 0, 0, ntxO, ntyB, ntOut);
    softmax_rows<<<BATCH, 256>>>(out, OUTDIM);
}

// round 16
// speedup vs baseline: 1.0992x; 1.0992x over previous
#include <cuda_runtime.h>
#include <cuda_bf16.h>
#include <cuda_fp16.h>
#include <cstddef>
#include <cstdint>

// ---------------------------------------------------------------------------
// TransNet, mma.sync fp16 GEMM (round-14 structure: launch-grid tiles).
//   Layer solve:  v·(cI + dt^2 W^T W) = rhs_v + dt·rhs_u@W
//   u_out = -u = dt·v@W^T - rhs_u,  v_out = -v
//   (cI + dt^2 K)^{-1} ≈ (1/c)(I - aK)   [first-order Neumann]
// All-fp16 dataflow (fp32 only for K and logits). Minv stored as 1024*Minv.
// Block 128x64, BK=64 (128B rows, SW128), 8 warps 32x32, 3-stage, 3 CTA/SM.
// ---------------------------------------------------------------------------

#define BATCH   8192
#define UNITS   1024
#define INDIM   2048
#define OUTDIM  1000
#define U2      (UNITS * UNITS)

static const float DT     = 0.1f;
static const float CCONST = 11.0f;           // 1 + dt/eps
static const float ACONST = 0.01f / 11.0f;   // dt^2 / c

// ------------------------------- scratch (16B+ aligned) --------------------
__device__ __align__(256) float g_s1[3 * U2];                    // K fp32 x3

__device__ __align__(256) unsigned short g_x16[BATCH * INDIM];   // fp16 x
__device__ __align__(256) unsigned short g_win16[UNITS * INDIM]; // fp16 W_in
__device__ __align__(256) unsigned short g_wo16[OUTDIM * UNITS]; // fp16 W_out
__device__ __align__(256) unsigned short g_P0[BATCH * UNITS];    // fp16 act
__device__ __align__(256) unsigned short g_P1[BATCH * UNITS];    // fp16 act
__device__ __align__(256) unsigned short g_P2[BATCH * UNITS];    // fp16 V
__device__ __align__(256) unsigned short g_rv16[BATCH * UNITS];  // fp16 Rv
__device__ __align__(256) unsigned short g_w16[3 * U2];          // fp16 W x3
__device__ __align__(256) unsigned short g_t16[3 * U2];          // fp16 W^T x3
__device__ __align__(256) unsigned short g_mi16[3 * U2];         // fp16 1024*Minv x3

// ------------------------------ helpers ------------------------------------
__device__ __forceinline__ uint32_t smem_u32(const void* p) {
    uint32_t a;
    asm("{ .reg .u64 t; cvta.to.shared.u64 t, %1; cvt.u32.u64 %0, t; }"
        : "=r"(a) : "l"(p));
    return a;
}

__device__ __forceinline__ void cp16(uint32_t dst, const void* src, bool inb) {
    int sz = inb ? 16 : 0;
    asm volatile(
        "{\n\t.reg .u64 g;\n\tcvta.to.global.u64 g, %1;\n\t"
        "cp.async.cg.shared.global [%0], [g], 16, %2;\n\t}"
        :: "r"(dst), "l"(src), "r"(sz) : "memory");
}
__device__ __forceinline__ void cp_commit() {
    asm volatile("cp.async.commit_group;" ::: "memory");
}
__device__ __forceinline__ void cp_wait1() {
    asm volatile("cp.async.wait_group 1;" ::: "memory");
}

__device__ __forceinline__ void mma_h(float* d, const uint32_t* a, const uint32_t* b) {
    asm volatile(
        "mma.sync.aligned.m16n8k16.row.col.f32.f16.f16.f32 "
        "{%0,%1,%2,%3}, {%4,%5,%6,%7}, {%8,%9}, {%0,%1,%2,%3};"
        : "+f"(d[0]), "+f"(d[1]), "+f"(d[2]), "+f"(d[3])
        : "r"(a[0]), "r"(a[1]), "r"(a[2]), "r"(a[3]), "r"(b[0]), "r"(b[1]));
}

__device__ __forceinline__ void ldsm4(uint32_t* r, uint32_t addr) {
    asm volatile("ldmatrix.sync.aligned.m8n8.x4.shared.b16 {%0,%1,%2,%3}, [%4];"
        : "=r"(r[0]), "=r"(r[1]), "=r"(r[2]), "=r"(r[3]) : "r"(addr));
}

__device__ __forceinline__ unsigned short f2h(float x) {
    return __half_as_ushort(__float2half_rn(x));
}
__device__ __forceinline__ float h2f(unsigned short x) {
    return __half2float(__ushort_as_half(x));
}

// --------------------------- GEMM kernel -------------------------------------
// d[m,n] = alpha*sum_k A[m,k]B[n,k] (+bias[n]) (+add_scale*fp16 addp16[m,n])
// Plain mode (bias2==null): C=d fp32 (opt), Ch=fp16(d) (opt).
// rhs mode (bias2!=null):   Ru = d + 0.1*bias2[n]; Ch=fp16(Ru);
//                           Rv = 10*relu(d) + (vprev16? svv*vprev16 : relu(d));
//                           Crelu16=fp16(Rv).
// Batch via blockIdx.z with element strides zsA/zsB/zsC.
// Block 128x64, BK=64 (128B rows, SW128); 8 warps, warp tile 32x32.
#define BM 128
#define BN 64
#define BK 64
#define A_T 16384u
#define STAGE 24576u
#define NSTAGE 3
#define SM_H (1024 + NSTAGE * STAGE)    // 74752

__global__ __launch_bounds__(256, 3) void gemm_h16(
    const unsigned short* __restrict__ A, const unsigned short* __restrict__ B,
    float* __restrict__ C, unsigned short* __restrict__ Ch,
    unsigned short* __restrict__ Crelu16,
    int M, int N, int K, float alpha,
    const float* __restrict__ bias,
    const unsigned short* __restrict__ addp16, float add_scale,
    const float* __restrict__ bias2,
    const unsigned short* __restrict__ vprev16, float svv,
    long zsA, long zsB, long zsC)
{
    extern __shared__ char smem[];
    const uint32_t sbase = smem_u32(smem) + 1024;
    const int tid  = threadIdx.x;
    const int wid  = tid >> 5;
    const int lane = tid & 31;
    const int bm = blockIdx.y * BM;
    const int bn = blockIdx.x * BN;
    const int nc = K / BK;
    const long z = blockIdx.z;
    A += z * zsA;  B += z * zsB;

    // ---- cp.async: per-thread slots (4 A rows + 2 B rows, stride 32) --------
    const int arow = tid >> 3;          // 0..31
    const int ach  = tid & 7;           // 16B chunk in 128B row
    const unsigned short* gA = A + (size_t)(bm + arow) * K + ach * 8;
    const unsigned short* gB = B + (size_t)(bn + arow) * K + ach * 8;
    const size_t rstep = (size_t)32 * K;
    bool inA[4], inB[2];
#pragma unroll
    for (int i = 0; i < 4; ++i) inA[i] = (bm + arow + 32 * i) < M;
#pragma unroll
    for (int i = 0; i < 2; ++i) inB[i] = (bn + arow + 32 * i) < N;
    const uint32_t of0 = (uint32_t)arow * 128u
                       + (uint32_t)((ach ^ (arow & 7)) << 4);

    auto issue_stage = [&](int c) {
        const int k0 = c * BK;
        const uint32_t sd = sbase + (uint32_t)(c % NSTAGE) * STAGE;
#pragma unroll
        for (int i = 0; i < 4; ++i)
            cp16(sd + of0 + (uint32_t)i * 4096u, gA + (size_t)i * rstep + k0, inA[i]);
#pragma unroll
        for (int i = 0; i < 2; ++i)
            cp16(sd + A_T + of0 + (uint32_t)i * 4096u, gB + (size_t)i * rstep + k0, inB[i]);
        cp_commit();
    };

    // ---- warp tiling: warp (wm, wn) = rows [wm*32,+32) x cols [wn*32,+32) ---
    const int wm = wid & 3;
    const int wn = wid >> 2;
    const int r  = lane >> 2;
    const int c2 = (lane & 3) * 2;

    const int q    = lane >> 3;           // 0..3
    const int rin  = lane & 7;
    const uint32_t a_row = (uint32_t)(wm * 32 + (q & 1) * 8 + rin) * 128u;
    const int a_sel = q >> 1;
    const uint32_t b_row = (uint32_t)(wn * 32 + (q >> 1) * 8 + rin) * 128u + A_T;
    const int b_sel = q & 1;

    float acc[2][4][4];
#pragma unroll
    for (int a = 0; a < 2; ++a)
#pragma unroll
        for (int b = 0; b < 4; ++b)
#pragma unroll
            for (int k = 0; k < 4; ++k) acc[a][b][k] = 0.0f;

    issue_stage(0);
    if (nc > 1) issue_stage(1);

    for (int c = 0; c < nc; ++c) {
        cp_wait1();
        __syncthreads();
        if (c + 2 < nc) issue_stage(c + 2);

        const uint32_t st = sbase + (uint32_t)(c % NSTAGE) * STAGE;

#pragma unroll
        for (int ks = 0; ks < 4; ++ks) {
            const uint32_t aoff = (uint32_t)(((ks * 2 + a_sel) ^ rin)) << 4;
            const uint32_t boff = (uint32_t)(((ks * 2 + b_sel) ^ rin)) << 4;

            uint32_t a[2][4];
            ldsm4(a[0], st + a_row + aoff);
            ldsm4(a[1], st + a_row + 2048u + aoff);   // +16 rows

            uint32_t b[4][2];
#pragma unroll
            for (int p = 0; p < 2; ++p) {
                uint32_t r4[4];
                ldsm4(r4, st + b_row + (uint32_t)p * 2048u + boff);
                b[2 * p][0] = r4[0]; b[2 * p][1] = r4[1];
                b[2 * p + 1][0] = r4[2]; b[2 * p + 1][1] = r4[3];
            }

#pragma unroll
            for (int nt = 0; nt < 4; ++nt) {
                mma_h(acc[0][nt], a[0], b[nt]);
                mma_h(acc[1][nt], a[1], b[nt]);
            }
        }
    }
    __syncthreads();

    // ---- epilogue -----------------------------------------------------------
    if (C)       C       += z * zsC;
    if (Ch)      Ch      += z * zsC;
    if (Crelu16) Crelu16 += z * zsC;
#pragma unroll
    for (int mt = 0; mt < 2; ++mt) {
#pragma unroll
        for (int nt = 0; nt < 4; ++nt) {
            const int col = bn + wn * 32 + nt * 8 + c2;
            if (col >= N) continue;
            float bx = 0.f, by = 0.f;
            if (bias) { bx = bias[col]; by = bias[col + 1]; }
#pragma unroll
            for (int h = 0; h < 2; ++h) {
                const int m = bm + wm * 32 + mt * 16 + r + h * 8;
                float d0 = alpha * acc[mt][nt][2 * h + 0] + bx;
                float d1 = alpha * acc[mt][nt][2 * h + 1] + by;
                size_t idx = (size_t)m * N + col;
                if (addp16) {
                    ushort2 ap = *(const ushort2*)(addp16 + idx);
                    d0 += add_scale * h2f(ap.x);
                    d1 += add_scale * h2f(ap.y);
                }
                if (bias2) {
                    float r0 = fmaxf(d0, 0.f), r1 = fmaxf(d1, 0.f);
                    float rv0 = 10.f * r0, rv1 = 10.f * r1;
                    if (vprev16) {
                        ushort2 vp = *(const ushort2*)(vprev16 + idx);
                        rv0 += svv * h2f(vp.x); rv1 += svv * h2f(vp.y);
                    } else {
                        rv0 += r0; rv1 += r1;
                    }
                    *(ushort2*)(Crelu16 + idx) = make_ushort2(f2h(rv0), f2h(rv1));
                    d0 += 0.1f * bias2[col];
                    d1 += 0.1f * bias2[col + 1];
                }
                if (C)  *(float2*)(C + idx) = make_float2(d0, d1);
                if (Ch) *(ushort2*)(Ch + idx) = make_ushort2(f2h(d0), f2h(d1));
            }
        }
    }
}

// ----------------------------- elementwise ---------------------------------
// one launch converting all three fp32 inputs (x, W_in, W_out) to fp16
__global__ void tofp16_all(const float* __restrict__ s0, unsigned short* __restrict__ d0, int n0,
                           const float* __restrict__ s1, unsigned short* __restrict__ d1, int n1,
                           const float* __restrict__ s2, unsigned short* __restrict__ d2, int n2)
{
    int i = (blockIdx.x * blockDim.x + threadIdx.x) * 4;
    const float* s; unsigned short* d;
    if (i < n0)            { s = s0 + i;            d = d0 + i; }
    else if (i < n0 + n1)  { s = s1 + (i - n0);     d = d1 + (i - n0); }
    else if (i < n0 + n1 + n2) { s = s2 + (i - n0 - n1); d = d2 + (i - n0 - n1); }
    else return;
    float4 v = *(const float4*)s;
    *(ushort4*)d = make_ushort4(f2h(v.x), f2h(v.y), f2h(v.z), f2h(v.w));
}

// batched over 3 layers: fp16 W_z -> w16+z*U2; fp16 W_z^T -> t16+z*U2
__global__ void weight_prep3(unsigned short* __restrict__ w16,
                             unsigned short* __restrict__ t16,
                             const float* __restrict__ W0,
                             const float* __restrict__ W1,
                             const float* __restrict__ W2, int n)
{
    __shared__ float t[32][33];
    const int z = blockIdx.z;
    const float* W = (z == 0) ? W0 : (z == 1) ? W1 : W2;
    unsigned short* w = w16 + (size_t)z * U2;
    unsigned short* tt = t16 + (size_t)z * U2;
    int x = blockIdx.x * 32 + threadIdx.x;
    int y = blockIdx.y * 32 + threadIdx.y;
    float v = W[(size_t)y * n + x];
    t[threadIdx.y][threadIdx.x] = v;
    w[(size_t)y * n + x] = f2h(v);
    __syncthreads();
    int ox = blockIdx.y * 32 + threadIdx.x;
    int oy = blockIdx.x * 32 + threadIdx.y;
    tt[(size_t)oy * n + ox] = f2h(t[threadIdx.x][threadIdx.y]);
}

// batched: d16[i] = fp16( scale*src[i] + diag on per-matrix diagonal )
__global__ void scale_diag16(unsigned short* __restrict__ d16,
                             const float* __restrict__ src,
                             float scale, float diag, int dim, int total)
{
    int i = blockIdx.x * blockDim.x + threadIdx.x;
    if (i < total) {
        float v = scale * src[i];
        int row = (i / dim) % dim;
        if (row == (i % dim)) v += diag;
        d16[i] = f2h(v);
    }
}

__global__ void softmax_rows(float* __restrict__ data, int cols)
{
    int row = blockIdx.x;
    float* d = data + (size_t)row * cols;
    __shared__ float sm[32];
    int tid = threadIdx.x, lane = tid & 31, warp = tid >> 5;
    int nwarp = blockDim.x >> 5;

    float m = -3.4e38f;
    for (int i = tid; i < cols; i += blockDim.x) m = fmaxf(m, d[i]);
#pragma unroll
    for (int o = 16; o; o >>= 1) m = fmaxf(m, __shfl_xor_sync(0xffffffffu, m, o));
    if (lane == 0) sm[warp] = m;
    __syncthreads();
    if (warp == 0) {
        float t = (lane < nwarp) ? sm[lane] : -3.4e38f;
#pragma unroll
        for (int o = 16; o; o >>= 1) t = fmaxf(t, __shfl_xor_sync(0xffffffffu, t, o));
        if (lane == 0) sm[0] = t;
    }
    __syncthreads();
    float mx = sm[0];
    __syncthreads();

    float s = 0.0f;
    for (int i = tid; i < cols; i += blockDim.x) {
        float e = expf(d[i] - mx);
        d[i] = e;
        s += e;
    }
#pragma unroll
    for (int o = 16; o; o >>= 1) s += __shfl_xor_sync(0xffffffffu, s, o);
    if (lane == 0) sm[warp] = s;
    __syncthreads();
    if (warp == 0) {
        float t = (lane < nwarp) ? sm[lane] : 0.0f;
#pragma unroll
        for (int o = 16; o; o >>= 1) t += __shfl_xor_sync(0xffffffffu, t, o);
        if (lane == 0) sm[0] = t;
    }
    __syncthreads();
    float inv = 1.0f / sm[0];
    for (int i = tid; i < cols; i += blockDim.x) d[i] *= inv;
}

// ---------------------------------------------------------------------------
extern "C" void kernel_launch(void* const* d_in, const int* in_sizes, int n_in,
                              void* d_out, int out_size)
{
    const float* x     = (const float*)d_in[0];
    const float* W_in  = (const float*)d_in[1];
    const float* b_in  = (const float*)d_in[2];
    const float* Ws[3] = {(const float*)d_in[3], (const float*)d_in[5], (const float*)d_in[7]};
    const float* bs[3] = {(const float*)d_in[4], (const float*)d_in[6], (const float*)d_in[8]};
    const float* W_out = (const float*)d_in[9];
    const float* b_out = (const float*)d_in[10];
    float* out = (float*)d_out;

    cudaFuncSetAttribute(gemm_h16, cudaFuncAttributeMaxDynamicSharedMemorySize, SM_H);

    float* s1;
    cudaGetSymbolAddress((void**)&s1, g_s1);
    unsigned short *x16, *win16, *wo16, *P0, *P1, *P2, *rv16, *w16, *t16, *mi16;
    cudaGetSymbolAddress((void**)&x16, g_x16);
    cudaGetSymbolAddress((void**)&win16, g_win16);
    cudaGetSymbolAddress((void**)&wo16, g_wo16);
    cudaGetSymbolAddress((void**)&P0, g_P0);
    cudaGetSymbolAddress((void**)&P1, g_P1);
    cudaGetSymbolAddress((void**)&P2, g_P2);
    cudaGetSymbolAddress((void**)&rv16, g_rv16);
    cudaGetSymbolAddress((void**)&w16, g_w16);
    cudaGetSymbolAddress((void**)&t16, g_t16);
    cudaGetSymbolAddress((void**)&mi16, g_mi16);

    dim3 gBig(UNITS / BN, BATCH / BM, 1);              // (16, 64)
    dim3 gK(UNITS / BN, UNITS / BM, 3);                // (16, 8, 3) batched
    dim3 gOut((OUTDIM + BN - 1) / BN, BATCH / BM, 1);  // (16, 64)
    dim3 tblk(32, 32), tgrid3(UNITS / 32, UNITS / 32, 3);

    // one-time fp16 conversions (single launch) + batched weight pipeline
    const int n0 = BATCH * INDIM, n1 = UNITS * INDIM, n2 = OUTDIM * UNITS;
    tofp16_all<<<((n0 + n1 + n2) / 4 + 255) / 256, 256>>>(x, x16, n0,
                                                          W_in, win16, n1,
                                                          W_out, wo16, n2);
    weight_prep3<<<tgrid3, tblk>>>(w16, t16, Ws[0], Ws[1], Ws[2], UNITS);
    // K_z = W_z^T W_z  (batched, fp32 out)
    gemm_h16<<<gK, 256, SM_H>>>(t16, t16, s1, nullptr, nullptr,
                                UNITS, UNITS, UNITS, 1.0f, nullptr,
                                nullptr, 0.0f, nullptr, nullptr, 0.0f,
                                (long)U2, (long)U2, (long)U2);
    // mi16_z = fp16(1024 * Minv_z)
    scale_diag16<<<(3 * U2 + 255) / 256, 256>>>(mi16, s1,
                                                -1024.0f * ACONST / CCONST,
                                                1024.0f / CCONST, UNITS, 3 * U2);

    // Input GEMM, rhs mode: d = x@W_in^T + b_in
    //   Ru0 fp16 -> P0, Rv0 = 11*relu(d) fp16 -> rv16
    gemm_h16<<<gBig, 256, SM_H>>>(x16, win16, nullptr, P0, rv16,
                                  BATCH, UNITS, INDIM, 1.0f, b_in,
                                  nullptr, 0.0f, bs[0], nullptr, 0.0f,
                                  0, 0, 0);

    unsigned short* ru = P0;      // fp16 Ru_l
    unsigned short* sc = P1;      // fp16 scratch (r, then next Ru)

    for (int l = 0; l < 3; ++l) {
        unsigned short* wl  = w16  + (size_t)l * U2;
        unsigned short* tl  = t16  + (size_t)l * U2;
        unsigned short* mil = mi16 + (size_t)l * U2;

        // r = dt*Ru@W + Rv  (B = W^T) -> fp16 sc
        gemm_h16<<<gBig, 256, SM_H>>>(ru, tl, nullptr, sc, nullptr,
                                      BATCH, UNITS, UNITS, DT, nullptr,
                                      rv16, 1.0f, nullptr, nullptr, 0.0f,
                                      0, 0, 0);
        // V = r @ (1024*Minv) / 1024 -> fp16 P2
        gemm_h16<<<gBig, 256, SM_H>>>(sc, mil, nullptr, P2, nullptr,
                                      BATCH, UNITS, UNITS, 1.0f / 1024.0f, nullptr,
                                      nullptr, 0.0f, nullptr, nullptr, 0.0f,
                                      0, 0, 0);
        // u_out = dt*V@W^T - Ru ; rhs mode emits Ru_{l+1} fp16 -> sc, Rv -> rv16
        if (l < 2) {
            gemm_h16<<<gBig, 256, SM_H>>>(P2, wl, nullptr, sc, rv16,
                                          BATCH, UNITS, UNITS, DT, nullptr,
                                          ru, -1.0f, bs[l + 1], P2, -1.0f,
                                          0, 0, 0);
        } else {
            gemm_h16<<<gBig, 256, SM_H>>>(P2, wl, nullptr, sc, nullptr,
                                          BATCH, UNITS, UNITS, DT, nullptr,
                                          ru, -1.0f, nullptr, nullptr, 0.0f,
                                          0, 0, 0);
        }
        unsigned short* t = ru; ru = sc; sc = t;
    }

    // logits = u @ W_out^T + b_out -> out ; softmax
    gemm_h16<<<gOut, 256, SM_H>>>(ru, wo16, out, nullptr, nullptr,
                                  BATCH, OUTDIM, UNITS, 1.0f, b_out,
                                  nullptr, 0.0f, nullptr, nullptr, 0.0f,
                                  0, 0, 0);
    softmax_rows<<<BATCH, 256>>>(out, OUTDIM);
}

// round 17
// speedup vs baseline: 1.1251x; 1.0236x over previous
#include <cuda_runtime.h>
#include <cuda_bf16.h>
#include <cuda_fp16.h>
#include <cstddef>
#include <cstdint>

// ---------------------------------------------------------------------------
// TransNet, mma.sync fp16 GEMM (launch-grid tiles, fused periphery).
//   Layer solve:  v·(cI + dt^2 W^T W) = rhs_v + dt·rhs_u@W
//   u_out = -u = dt·v@W^T - rhs_u,  v_out = -v
//   (cI + dt^2 K)^{-1} ≈ (1/c)(I - aK)   [first-order Neumann]
// All-fp16 dataflow (fp32 only for logits). Minv (as 1024*Minv fp16) is
// emitted directly by the K-GEMM epilogue (diag_add fusion).
// Block 128x64, BK=64 (128B rows, SW128), 8 warps 32x32, 3-stage, 3 CTA/SM.
// ---------------------------------------------------------------------------

#define BATCH   8192
#define UNITS   1024
#define INDIM   2048
#define OUTDIM  1000
#define U2      (UNITS * UNITS)

static const float DT     = 0.1f;
static const float CCONST = 11.0f;           // 1 + dt/eps
static const float ACONST = 0.01f / 11.0f;   // dt^2 / c

// ------------------------------- scratch (16B+ aligned) --------------------
__device__ __align__(256) unsigned short g_x16[BATCH * INDIM];   // fp16 x
__device__ __align__(256) unsigned short g_win16[UNITS * INDIM]; // fp16 W_in
__device__ __align__(256) unsigned short g_wo16[OUTDIM * UNITS]; // fp16 W_out
__device__ __align__(256) unsigned short g_P0[BATCH * UNITS];    // fp16 act
__device__ __align__(256) unsigned short g_P1[BATCH * UNITS];    // fp16 act
__device__ __align__(256) unsigned short g_P2[BATCH * UNITS];    // fp16 V
__device__ __align__(256) unsigned short g_rv16[BATCH * UNITS];  // fp16 Rv
__device__ __align__(256) unsigned short g_w16[3 * U2];          // fp16 W x3
__device__ __align__(256) unsigned short g_t16[3 * U2];          // fp16 W^T x3
__device__ __align__(256) unsigned short g_mi16[3 * U2];         // fp16 1024*Minv x3

// ------------------------------ helpers ------------------------------------
__device__ __forceinline__ uint32_t smem_u32(const void* p) {
    uint32_t a;
    asm("{ .reg .u64 t; cvta.to.shared.u64 t, %1; cvt.u32.u64 %0, t; }"
        : "=r"(a) : "l"(p));
    return a;
}

__device__ __forceinline__ void cp16(uint32_t dst, const void* src, bool inb) {
    int sz = inb ? 16 : 0;
    asm volatile(
        "{\n\t.reg .u64 g;\n\tcvta.to.global.u64 g, %1;\n\t"
        "cp.async.cg.shared.global [%0], [g], 16, %2;\n\t}"
        :: "r"(dst), "l"(src), "r"(sz) : "memory");
}
__device__ __forceinline__ void cp_commit() {
    asm volatile("cp.async.commit_group;" ::: "memory");
}
__device__ __forceinline__ void cp_wait1() {
    asm volatile("cp.async.wait_group 1;" ::: "memory");
}

__device__ __forceinline__ void mma_h(float* d, const uint32_t* a, const uint32_t* b) {
    asm volatile(
        "mma.sync.aligned.m16n8k16.row.col.f32.f16.f16.f32 "
        "{%0,%1,%2,%3}, {%4,%5,%6,%7}, {%8,%9}, {%0,%1,%2,%3};"
        : "+f"(d[0]), "+f"(d[1]), "+f"(d[2]), "+f"(d[3])
        : "r"(a[0]), "r"(a[1]), "r"(a[2]), "r"(a[3]), "r"(b[0]), "r"(b[1]));
}

__device__ __forceinline__ void ldsm4(uint32_t* r, uint32_t addr) {
    asm volatile("ldmatrix.sync.aligned.m8n8.x4.shared.b16 {%0,%1,%2,%3}, [%4];"
        : "=r"(r[0]), "=r"(r[1]), "=r"(r[2]), "=r"(r[3]) : "r"(addr));
}

__device__ __forceinline__ unsigned short f2h(float x) {
    return __half_as_ushort(__float2half_rn(x));
}
__device__ __forceinline__ float h2f(unsigned short x) {
    return __half2float(__ushort_as_half(x));
}

// --------------------------- GEMM kernel -------------------------------------
// d[m,n] = alpha*sum_k A[m,k]B[n,k] (+bias[n]) (+add_scale*fp16 addp16[m,n])
//          (+diag_add on m==n, for fused Minv generation)
// Plain mode (bias2==null): C=d fp32 (opt), Ch=fp16(d) (opt).
// rhs mode (bias2!=null):   Ru = d + 0.1*bias2[n]; Ch=fp16(Ru);
//                           Rv = 10*relu(d) + (vprev16? svv*vprev16 : relu(d));
//                           Crelu16=fp16(Rv).
// Batch via blockIdx.z with element strides zsA/zsB/zsC.
// Block 128x64, BK=64 (128B rows, SW128); 8 warps, warp tile 32x32.
#define BM 128
#define BN 64
#define BK 64
#define A_T 16384u
#define STAGE 24576u
#define NSTAGE 3
#define SM_H (1024 + NSTAGE * STAGE)    // 74752

__global__ __launch_bounds__(256, 3) void gemm_h16(
    const unsigned short* __restrict__ A, const unsigned short* __restrict__ B,
    float* __restrict__ C, unsigned short* __restrict__ Ch,
    unsigned short* __restrict__ Crelu16,
    int M, int N, int K, float alpha, float diag_add,
    const float* __restrict__ bias,
    const unsigned short* __restrict__ addp16, float add_scale,
    const float* __restrict__ bias2,
    const unsigned short* __restrict__ vprev16, float svv,
    long zsA, long zsB, long zsC)
{
    extern __shared__ char smem[];
    const uint32_t sbase = smem_u32(smem) + 1024;
    const int tid  = threadIdx.x;
    const int wid  = tid >> 5;
    const int lane = tid & 31;
    const int bm = blockIdx.y * BM;
    const int bn = blockIdx.x * BN;
    const int nc = K / BK;
    const long z = blockIdx.z;
    A += z * zsA;  B += z * zsB;

    // ---- cp.async: per-thread slots (4 A rows + 2 B rows, stride 32) --------
    const int arow = tid >> 3;          // 0..31
    const int ach  = tid & 7;           // 16B chunk in 128B row
    const unsigned short* gA = A + (size_t)(bm + arow) * K + ach * 8;
    const unsigned short* gB = B + (size_t)(bn + arow) * K + ach * 8;
    const size_t rstep = (size_t)32 * K;
    bool inA[4], inB[2];
#pragma unroll
    for (int i = 0; i < 4; ++i) inA[i] = (bm + arow + 32 * i) < M;
#pragma unroll
    for (int i = 0; i < 2; ++i) inB[i] = (bn + arow + 32 * i) < N;
    const uint32_t of0 = (uint32_t)arow * 128u
                       + (uint32_t)((ach ^ (arow & 7)) << 4);

    auto issue_stage = [&](int c) {
        const int k0 = c * BK;
        const uint32_t sd = sbase + (uint32_t)(c % NSTAGE) * STAGE;
#pragma unroll
        for (int i = 0; i < 4; ++i)
            cp16(sd + of0 + (uint32_t)i * 4096u, gA + (size_t)i * rstep + k0, inA[i]);
#pragma unroll
        for (int i = 0; i < 2; ++i)
            cp16(sd + A_T + of0 + (uint32_t)i * 4096u, gB + (size_t)i * rstep + k0, inB[i]);
        cp_commit();
    };

    // ---- warp tiling: warp (wm, wn) = rows [wm*32,+32) x cols [wn*32,+32) ---
    const int wm = wid & 3;
    const int wn = wid >> 2;
    const int r  = lane >> 2;
    const int c2 = (lane & 3) * 2;

    const int q    = lane >> 3;           // 0..3
    const int rin  = lane & 7;
    const uint32_t a_row = (uint32_t)(wm * 32 + (q & 1) * 8 + rin) * 128u;
    const int a_sel = q >> 1;
    const uint32_t b_row = (uint32_t)(wn * 32 + (q >> 1) * 8 + rin) * 128u + A_T;
    const int b_sel = q & 1;

    float acc[2][4][4];
#pragma unroll
    for (int a = 0; a < 2; ++a)
#pragma unroll
        for (int b = 0; b < 4; ++b)
#pragma unroll
            for (int k = 0; k < 4; ++k) acc[a][b][k] = 0.0f;

    issue_stage(0);
    if (nc > 1) issue_stage(1);

    for (int c = 0; c < nc; ++c) {
        cp_wait1();
        __syncthreads();
        if (c + 2 < nc) issue_stage(c + 2);

        const uint32_t st = sbase + (uint32_t)(c % NSTAGE) * STAGE;

#pragma unroll
        for (int ks = 0; ks < 4; ++ks) {
            const uint32_t aoff = (uint32_t)(((ks * 2 + a_sel) ^ rin)) << 4;
            const uint32_t boff = (uint32_t)(((ks * 2 + b_sel) ^ rin)) << 4;

            uint32_t a[2][4];
            ldsm4(a[0], st + a_row + aoff);
            ldsm4(a[1], st + a_row + 2048u + aoff);   // +16 rows

            uint32_t b[4][2];
#pragma unroll
            for (int p = 0; p < 2; ++p) {
                uint32_t r4[4];
                ldsm4(r4, st + b_row + (uint32_t)p * 2048u + boff);
                b[2 * p][0] = r4[0]; b[2 * p][1] = r4[1];
                b[2 * p + 1][0] = r4[2]; b[2 * p + 1][1] = r4[3];
            }

#pragma unroll
            for (int nt = 0; nt < 4; ++nt) {
                mma_h(acc[0][nt], a[0], b[nt]);
                mma_h(acc[1][nt], a[1], b[nt]);
            }
        }
    }
    __syncthreads();

    // ---- epilogue -----------------------------------------------------------
    if (C)       C       += z * zsC;
    if (Ch)      Ch      += z * zsC;
    if (Crelu16) Crelu16 += z * zsC;
#pragma unroll
    for (int mt = 0; mt < 2; ++mt) {
#pragma unroll
        for (int nt = 0; nt < 4; ++nt) {
            const int col = bn + wn * 32 + nt * 8 + c2;
            if (col >= N) continue;
            float bx = 0.f, by = 0.f;
            if (bias) { bx = bias[col]; by = bias[col + 1]; }
#pragma unroll
            for (int h = 0; h < 2; ++h) {
                const int m = bm + wm * 32 + mt * 16 + r + h * 8;
                float d0 = alpha * acc[mt][nt][2 * h + 0] + bx;
                float d1 = alpha * acc[mt][nt][2 * h + 1] + by;
                size_t idx = (size_t)m * N + col;
                if (diag_add != 0.0f) {
                    if (m == col)     d0 += diag_add;
                    if (m == col + 1) d1 += diag_add;
                }
                if (addp16) {
                    ushort2 ap = *(const ushort2*)(addp16 + idx);
                    d0 += add_scale * h2f(ap.x);
                    d1 += add_scale * h2f(ap.y);
                }
                if (bias2) {
                    float r0 = fmaxf(d0, 0.f), r1 = fmaxf(d1, 0.f);
                    float rv0 = 10.f * r0, rv1 = 10.f * r1;
                    if (vprev16) {
                        ushort2 vp = *(const ushort2*)(vprev16 + idx);
                        rv0 += svv * h2f(vp.x); rv1 += svv * h2f(vp.y);
                    } else {
                        rv0 += r0; rv1 += r1;
                    }
                    *(ushort2*)(Crelu16 + idx) = make_ushort2(f2h(rv0), f2h(rv1));
                    d0 += 0.1f * bias2[col];
                    d1 += 0.1f * bias2[col + 1];
                }
                if (C)  *(float2*)(C + idx) = make_float2(d0, d1);
                if (Ch) *(ushort2*)(Ch + idx) = make_ushort2(f2h(d0), f2h(d1));
            }
        }
    }
}

// ----------------------------- elementwise ---------------------------------
// one launch converting all three fp32 inputs (x, W_in, W_out) to fp16
__global__ void tofp16_all(const float* __restrict__ s0, unsigned short* __restrict__ d0, int n0,
                           const float* __restrict__ s1, unsigned short* __restrict__ d1, int n1,
                           const float* __restrict__ s2, unsigned short* __restrict__ d2, int n2)
{
    int i = (blockIdx.x * blockDim.x + threadIdx.x) * 4;
    const float* s; unsigned short* d;
    if (i < n0)            { s = s0 + i;            d = d0 + i; }
    else if (i < n0 + n1)  { s = s1 + (i - n0);     d = d1 + (i - n0); }
    else if (i < n0 + n1 + n2) { s = s2 + (i - n0 - n1); d = d2 + (i - n0 - n1); }
    else return;
    float4 v = *(const float4*)s;
    *(ushort4*)d = make_ushort4(f2h(v.x), f2h(v.y), f2h(v.z), f2h(v.w));
}

// batched over 3 layers: fp16 W_z -> w16+z*U2; fp16 W_z^T -> t16+z*U2
__global__ void weight_prep3(unsigned short* __restrict__ w16,
                             unsigned short* __restrict__ t16,
                             const float* __restrict__ W0,
                             const float* __restrict__ W1,
                             const float* __restrict__ W2, int n)
{
    __shared__ float t[32][33];
    const int z = blockIdx.z;
    const float* W = (z == 0) ? W0 : (z == 1) ? W1 : W2;
    unsigned short* w = w16 + (size_t)z * U2;
    unsigned short* tt = t16 + (size_t)z * U2;
    int x = blockIdx.x * 32 + threadIdx.x;
    int y = blockIdx.y * 32 + threadIdx.y;
    float v = W[(size_t)y * n + x];
    t[threadIdx.y][threadIdx.x] = v;
    w[(size_t)y * n + x] = f2h(v);
    __syncthreads();
    int ox = blockIdx.y * 32 + threadIdx.x;
    int oy = blockIdx.x * 32 + threadIdx.y;
    tt[(size_t)oy * n + ox] = f2h(t[threadIdx.x][threadIdx.y]);
}

// register-resident softmax: 256 threads, each owns one float4 slice (cols<=1024)
__global__ void softmax_rows(float* __restrict__ data, int cols)
{
    const int row = blockIdx.x;
    float* d = data + (size_t)row * cols;
    const int tid = threadIdx.x, lane = tid & 31, warp = tid >> 5;
    const bool ok = (tid * 4 < cols);
    __shared__ float sm[8];

    float4 v = make_float4(-3.4e38f, -3.4e38f, -3.4e38f, -3.4e38f);
    if (ok) v = *(const float4*)(d + tid * 4);

    float m = fmaxf(fmaxf(v.x, v.y), fmaxf(v.z, v.w));
#pragma unroll
    for (int o = 16; o; o >>= 1) m = fmaxf(m, __shfl_xor_sync(0xffffffffu, m, o));
    if (lane == 0) sm[warp] = m;
    __syncthreads();
    if (warp == 0) {
        float t = sm[lane & 7];
#pragma unroll
        for (int o = 4; o; o >>= 1) t = fmaxf(t, __shfl_xor_sync(0xffffffffu, t, o));
        if (lane == 0) sm[0] = t;
    }
    __syncthreads();
    const float mx = sm[0];
    __syncthreads();

    float s = 0.0f;
    if (ok) {
        v.x = expf(v.x - mx); v.y = expf(v.y - mx);
        v.z = expf(v.z - mx); v.w = expf(v.w - mx);
        s = v.x + v.y + v.z + v.w;
    }
#pragma unroll
    for (int o = 16; o; o >>= 1) s += __shfl_xor_sync(0xffffffffu, s, o);
    if (lane == 0) sm[warp] = s;
    __syncthreads();
    if (warp == 0) {
        float t = sm[lane & 7];
#pragma unroll
        for (int o = 4; o; o >>= 1) t += __shfl_xor_sync(0xffffffffu, t, o);
        if (lane == 0) sm[0] = t;
    }
    __syncthreads();
    const float inv = 1.0f / sm[0];
    if (ok) {
        v.x *= inv; v.y *= inv; v.z *= inv; v.w *= inv;
        *(float4*)(d + tid * 4) = v;
    }
}

// ---------------------------------------------------------------------------
extern "C" void kernel_launch(void* const* d_in, const int* in_sizes, int n_in,
                              void* d_out, int out_size)
{
    const float* x     = (const float*)d_in[0];
    const float* W_in  = (const float*)d_in[1];
    const float* b_in  = (const float*)d_in[2];
    const float* Ws[3] = {(const float*)d_in[3], (const float*)d_in[5], (const float*)d_in[7]};
    const float* bs[3] = {(const float*)d_in[4], (const float*)d_in[6], (const float*)d_in[8]};
    const float* W_out = (const float*)d_in[9];
    const float* b_out = (const float*)d_in[10];
    float* out = (float*)d_out;

    cudaFuncSetAttribute(gemm_h16, cudaFuncAttributeMaxDynamicSharedMemorySize, SM_H);

    unsigned short *x16, *win16, *wo16, *P0, *P1, *P2, *rv16, *w16, *t16, *mi16;
    cudaGetSymbolAddress((void**)&x16, g_x16);
    cudaGetSymbolAddress((void**)&win16, g_win16);
    cudaGetSymbolAddress((void**)&wo16, g_wo16);
    cudaGetSymbolAddress((void**)&P0, g_P0);
    cudaGetSymbolAddress((void**)&P1, g_P1);
    cudaGetSymbolAddress((void**)&P2, g_P2);
    cudaGetSymbolAddress((void**)&rv16, g_rv16);
    cudaGetSymbolAddress((void**)&w16, g_w16);
    cudaGetSymbolAddress((void**)&t16, g_t16);
    cudaGetSymbolAddress((void**)&mi16, g_mi16);

    dim3 gBig(UNITS / BN, BATCH / BM, 1);              // (16, 64)
    dim3 gK(UNITS / BN, UNITS / BM, 3);                // (16, 8, 3) batched
    dim3 gOut((OUTDIM + BN - 1) / BN, BATCH / BM, 1);  // (16, 64)
    dim3 tblk(32, 32), tgrid3(UNITS / 32, UNITS / 32, 3);

    // one-time fp16 conversions (single launch) + batched weight pipeline
    const int n0 = BATCH * INDIM, n1 = UNITS * INDIM, n2 = OUTDIM * UNITS;
    tofp16_all<<<((n0 + n1 + n2) / 4 + 255) / 256, 256>>>(x, x16, n0,
                                                          W_in, win16, n1,
                                                          W_out, wo16, n2);
    weight_prep3<<<tgrid3, tblk>>>(w16, t16, Ws[0], Ws[1], Ws[2], UNITS);
    // mi16_z = fp16( -(1024 a/c) * W_z^T W_z + (1024/c) I )  -- fused epilogue
    gemm_h16<<<gK, 256, SM_H>>>(t16, t16, nullptr, mi16, nullptr,
                                UNITS, UNITS, UNITS,
                                -1024.0f * ACONST / CCONST, 1024.0f / CCONST,
                                nullptr, nullptr, 0.0f, nullptr, nullptr, 0.0f,
                                (long)U2, (long)U2, (long)U2);

    // Input GEMM, rhs mode: d = x@W_in^T + b_in
    //   Ru0 fp16 -> P0, Rv0 = 11*relu(d) fp16 -> rv16
    gemm_h16<<<gBig, 256, SM_H>>>(x16, win16, nullptr, P0, rv16,
                                  BATCH, UNITS, INDIM, 1.0f, 0.0f, b_in,
                                  nullptr, 0.0f, bs[0], nullptr, 0.0f,
                                  0, 0, 0);

    unsigned short* ru = P0;      // fp16 Ru_l
    unsigned short* sc = P1;      // fp16 scratch (r, then next Ru)

    for (int l = 0; l < 3; ++l) {
        unsigned short* wl  = w16  + (size_t)l * U2;
        unsigned short* tl  = t16  + (size_t)l * U2;
        unsigned short* mil = mi16 + (size_t)l * U2;

        // r = dt*Ru@W + Rv  (B = W^T) -> fp16 sc
        gemm_h16<<<gBig, 256, SM_H>>>(ru, tl, nullptr, sc, nullptr,
                                      BATCH, UNITS, UNITS, DT, 0.0f, nullptr,
                                      rv16, 1.0f, nullptr, nullptr, 0.0f,
                                      0, 0, 0);
        // V = r @ (1024*Minv) / 1024 -> fp16 P2
        gemm_h16<<<gBig, 256, SM_H>>>(sc, mil, nullptr, P2, nullptr,
                                      BATCH, UNITS, UNITS, 1.0f / 1024.0f, 0.0f,
                                      nullptr, nullptr, 0.0f,
                                      nullptr, nullptr, 0.0f,
                                      0, 0, 0);
        // u_out = dt*V@W^T - Ru ; rhs mode emits Ru_{l+1} fp16 -> sc, Rv -> rv16
        if (l < 2) {
            gemm_h16<<<gBig, 256, SM_H>>>(P2, wl, nullptr, sc, rv16,
                                          BATCH, UNITS, UNITS, DT, 0.0f, nullptr,
                                          ru, -1.0f, bs[l + 1], P2, -1.0f,
                                          0, 0, 0);
        } else {
            gemm_h16<<<gBig, 256, SM_H>>>(P2, wl, nullptr, sc, nullptr,
                                          BATCH, UNITS, UNITS, DT, 0.0f, nullptr,
                                          ru, -1.0f, nullptr, nullptr, 0.0f,
                                          0, 0, 0);
        }
        unsigned short* t = ru; ru = sc; sc = t;
    }

    // logits = u @ W_out^T + b_out -> out ; softmax
    gemm_h16<<<gOut, 256, SM_H>>>(ru, wo16, out, nullptr, nullptr,
                                  BATCH, OUTDIM, UNITS, 1.0f, 0.0f, b_out,
                                  nullptr, 0.0f, nullptr, nullptr, 0.0f,
                                  0, 0, 0);
    softmax_rows<<<BATCH, 256>>>(out, OUTDIM);
}